// round 1
// baseline (speedup 1.0000x reference)
#include <cuda_runtime.h>
#include <math.h>

#define T_TOK 8192
#define D_DIM 1024
#define F_DIM 4096
#define E_NUM 8
#define A_TOT (T_TOK * 2)

// ---------------- scratch (device globals; no allocations allowed) ----------
__device__ int   g_cnt[E_NUM];
__device__ int   g_off[E_NUM];
__device__ int   g_cur[E_NUM];
__device__ int   g_top[T_TOK][2];
__device__ float g_gate[T_TOK][2];
__device__ int   g_rowtok[A_TOT];
__device__ float g_rowgate[A_TOT];
__device__ float g_h[(size_t)A_TOT * F_DIM];   // 268 MB hidden activations

// ---------------- init: zero output + counters ------------------------------
__global__ void zero_kernel(float* __restrict__ out) {
    size_t n = (size_t)T_TOK * D_DIM;
    for (size_t i = (size_t)blockIdx.x * blockDim.x + threadIdx.x; i < n;
         i += (size_t)gridDim.x * blockDim.x)
        out[i] = 0.0f;
    if (blockIdx.x == 0 && threadIdx.x < E_NUM) {
        g_cnt[threadIdx.x] = 0;
        g_cur[threadIdx.x] = 0;
    }
}

// ---------------- router: one warp per token --------------------------------
__global__ void router_kernel(const float* __restrict__ x,
                              const float* __restrict__ rw) {
    int gwarp = (blockIdx.x * blockDim.x + threadIdx.x) >> 5;
    int lane  = threadIdx.x & 31;
    if (gwarp >= T_TOK) return;
    const float* xr = x + (size_t)gwarp * D_DIM;

    float xv[32];
#pragma unroll
    for (int i = 0; i < 32; i++) xv[i] = xr[lane + 32 * i];

    float logits[E_NUM];
#pragma unroll
    for (int e = 0; e < E_NUM; e++) {
        float s = 0.0f;
#pragma unroll
        for (int i = 0; i < 32; i++)
            s += xv[i] * rw[(lane + 32 * i) * E_NUM + e];
#pragma unroll
        for (int o = 16; o > 0; o >>= 1)
            s += __shfl_xor_sync(0xffffffffu, s, o);
        logits[e] = s;
    }

    if (lane == 0) {
        // top-2 with first-occurrence tie-break (matches lax.top_k)
        int i0 = 0;
#pragma unroll
        for (int e = 1; e < E_NUM; e++)
            if (logits[e] > logits[i0]) i0 = e;
        int i1 = (i0 == 0) ? 1 : 0;
#pragma unroll
        for (int e = 0; e < E_NUM; e++) {
            if (e == i0) continue;
            if (logits[e] > logits[i1]) i1 = e;
        }
        // renormalized top-2 softmax gates, computed stably from logits
        float g0 = 1.0f / (1.0f + expf(logits[i1] - logits[i0]));
        float g1 = 1.0f - g0;
        g_top[gwarp][0]  = i0;
        g_top[gwarp][1]  = i1;
        g_gate[gwarp][0] = g0;
        g_gate[gwarp][1] = g1;
        atomicAdd(&g_cnt[i0], 1);
        atomicAdd(&g_cnt[i1], 1);
    }
}

// ---------------- exclusive prefix over 8 experts ---------------------------
__global__ void offsets_kernel() {
    if (threadIdx.x == 0 && blockIdx.x == 0) {
        int run = 0;
#pragma unroll
        for (int e = 0; e < E_NUM; e++) {
            g_off[e] = run;
            run += g_cnt[e];
            g_cur[e] = 0;
        }
    }
}

// ---------------- compact per-expert assignment lists ------------------------
__global__ void place_kernel() {
    int t = blockIdx.x * blockDim.x + threadIdx.x;
    if (t >= T_TOK) return;
#pragma unroll
    for (int s = 0; s < 2; s++) {
        int e = g_top[t][s];
        int p = g_off[e] + atomicAdd(&g_cur[e], 1);
        g_rowtok[p]  = t;
        g_rowgate[p] = g_gate[t][s];
    }
}

// ---------------- GELU (tanh approximation = jax.nn.gelu default) -----------
__device__ __forceinline__ float gelu_tanh(float v) {
    float c = 0.7978845608028654f * (v + 0.044715f * v * v * v);
    return 0.5f * v * (1.0f + tanhf(c));
}

// ---------------- GEMM1: H = gelu(gather(X) @ w1[e]),  K=1024, N=4096 -------
// 128x128 tile, BK=8, 256 threads, 8x8 microtile per thread
__global__ __launch_bounds__(256) void gemm1_kernel(
    const float* __restrict__ x, const float* __restrict__ w1) {
    const int e   = blockIdx.z;
    const int cnt = g_cnt[e];
    const int m0  = blockIdx.x * 128;
    if (m0 >= cnt) return;
    const int   base = g_off[e];
    const float* B   = w1 + (size_t)e * D_DIM * F_DIM;
    const int   n0   = blockIdx.y * 128;

    __shared__ float As[8][128];
    __shared__ float Bs[8][128];

    const int tid  = threadIdx.x;
    const int tx   = tid & 15;
    const int ty   = tid >> 4;
    const int aRow = tid >> 1;
    const int aCol = (tid & 1) * 4;
    const int bRow = tid >> 5;
    const int bCol = (tid & 31) * 4;

    const float* Arow = nullptr;
    if (m0 + aRow < cnt)
        Arow = x + (size_t)g_rowtok[base + m0 + aRow] * D_DIM;

    float acc[8][8];
#pragma unroll
    for (int i = 0; i < 8; i++)
#pragma unroll
        for (int j = 0; j < 8; j++) acc[i][j] = 0.0f;

    for (int k0 = 0; k0 < D_DIM; k0 += 8) {
        float4 av = Arow ? *(const float4*)(Arow + k0 + aCol)
                         : make_float4(0.f, 0.f, 0.f, 0.f);
        As[aCol + 0][aRow] = av.x;
        As[aCol + 1][aRow] = av.y;
        As[aCol + 2][aRow] = av.z;
        As[aCol + 3][aRow] = av.w;
        *(float4*)&Bs[bRow][bCol] =
            *(const float4*)(B + (size_t)(k0 + bRow) * F_DIM + n0 + bCol);
        __syncthreads();
#pragma unroll
        for (int k = 0; k < 8; k++) {
            float4 a0 = *(const float4*)&As[k][ty * 8];
            float4 a1 = *(const float4*)&As[k][ty * 8 + 4];
            float4 b0 = *(const float4*)&Bs[k][tx * 8];
            float4 b1 = *(const float4*)&Bs[k][tx * 8 + 4];
            float rm[8] = {a0.x, a0.y, a0.z, a0.w, a1.x, a1.y, a1.z, a1.w};
            float rn[8] = {b0.x, b0.y, b0.z, b0.w, b1.x, b1.y, b1.z, b1.w};
#pragma unroll
            for (int i = 0; i < 8; i++)
#pragma unroll
                for (int j = 0; j < 8; j++) acc[i][j] += rm[i] * rn[j];
        }
        __syncthreads();
    }

#pragma unroll
    for (int i = 0; i < 8; i++) {
        int row = m0 + ty * 8 + i;
        if (row < cnt) {
            float* op = &g_h[(size_t)(base + row) * F_DIM + n0 + tx * 8];
#pragma unroll
            for (int j = 0; j < 8; j++) op[j] = gelu_tanh(acc[i][j]);
        }
    }
}

// ---------------- GEMM2: out[tok] += gate * (H @ w2[e]),  K=4096, N=1024 ----
__global__ __launch_bounds__(256) void gemm2_kernel(
    const float* __restrict__ w2, float* __restrict__ out) {
    const int e   = blockIdx.z;
    const int cnt = g_cnt[e];
    const int m0  = blockIdx.x * 128;
    if (m0 >= cnt) return;
    const int   base = g_off[e];
    const float* B   = w2 + (size_t)e * F_DIM * D_DIM;
    const int   n0   = blockIdx.y * 128;

    __shared__ float As[8][128];
    __shared__ float Bs[8][128];

    const int tid  = threadIdx.x;
    const int tx   = tid & 15;
    const int ty   = tid >> 4;
    const int aRow = tid >> 1;
    const int aCol = (tid & 1) * 4;
    const int bRow = tid >> 5;
    const int bCol = (tid & 31) * 4;

    const float* Arow = nullptr;
    if (m0 + aRow < cnt)
        Arow = &g_h[(size_t)(base + m0 + aRow) * F_DIM];

    float acc[8][8];
#pragma unroll
    for (int i = 0; i < 8; i++)
#pragma unroll
        for (int j = 0; j < 8; j++) acc[i][j] = 0.0f;

    for (int k0 = 0; k0 < F_DIM; k0 += 8) {
        float4 av = Arow ? *(const float4*)(Arow + k0 + aCol)
                         : make_float4(0.f, 0.f, 0.f, 0.f);
        As[aCol + 0][aRow] = av.x;
        As[aCol + 1][aRow] = av.y;
        As[aCol + 2][aRow] = av.z;
        As[aCol + 3][aRow] = av.w;
        *(float4*)&Bs[bRow][bCol] =
            *(const float4*)(B + (size_t)(k0 + bRow) * D_DIM + n0 + bCol);
        __syncthreads();
#pragma unroll
        for (int k = 0; k < 8; k++) {
            float4 a0 = *(const float4*)&As[k][ty * 8];
            float4 a1 = *(const float4*)&As[k][ty * 8 + 4];
            float4 b0 = *(const float4*)&Bs[k][tx * 8];
            float4 b1 = *(const float4*)&Bs[k][tx * 8 + 4];
            float rm[8] = {a0.x, a0.y, a0.z, a0.w, a1.x, a1.y, a1.z, a1.w};
            float rn[8] = {b0.x, b0.y, b0.z, b0.w, b1.x, b1.y, b1.z, b1.w};
#pragma unroll
            for (int i = 0; i < 8; i++)
#pragma unroll
                for (int j = 0; j < 8; j++) acc[i][j] += rm[i] * rn[j];
        }
        __syncthreads();
    }

#pragma unroll
    for (int i = 0; i < 8; i++) {
        int row = m0 + ty * 8 + i;
        if (row < cnt) {
            int   tok  = g_rowtok[base + row];
            float gate = g_rowgate[base + row];
            float* op  = out + (size_t)tok * D_DIM + n0 + tx * 8;
#pragma unroll
            for (int j = 0; j < 8; j++) atomicAdd(op + j, gate * acc[i][j]);
        }
    }
}

// ---------------- launch ------------------------------------------------------
extern "C" void kernel_launch(void* const* d_in, const int* in_sizes, int n_in,
                              void* d_out, int out_size) {
    const float* x  = (const float*)d_in[0];
    const float* rw = (const float*)d_in[1];
    const float* w1 = (const float*)d_in[2];
    const float* w2 = (const float*)d_in[3];
    float*       out = (float*)d_out;

    zero_kernel<<<1024, 256>>>(out);
    router_kernel<<<(T_TOK * 32) / 256, 256>>>(x, rw);
    offsets_kernel<<<1, 32>>>();
    place_kernel<<<T_TOK / 256, 256>>>();

    dim3 g1(T_TOK * 2 / 128 / 2, F_DIM / 128, E_NUM);  // (64, 32, 8) worst case
    gemm1_kernel<<<dim3(64, F_DIM / 128, E_NUM), 256>>>(x, w1);
    gemm2_kernel<<<dim3(64, D_DIM / 128, E_NUM), 256>>>(w2, out);
}

// round 3
// speedup vs baseline: 3.2324x; 3.2324x over previous
#include <cuda_runtime.h>
#include <cuda_bf16.h>
#include <math.h>
#include <stdint.h>

#define T_TOK 8192
#define D_DIM 1024
#define F_DIM 4096
#define E_NUM 8
#define A_TOT (T_TOK * 2)

// ---------------- scratch (device globals; no allocations allowed) ----------
__device__ int   g_cnt[E_NUM];
__device__ int   g_off[E_NUM];
__device__ int   g_cur[E_NUM];
__device__ int   g_top[T_TOK][2];
__device__ float g_gate[T_TOK][2];
__device__ int   g_rowtok[A_TOT];
__device__ float g_rowgate[A_TOT];

// bf16 hi/lo planes (raw ushort bits)
__device__ unsigned short g_x_hi[(size_t)T_TOK * D_DIM];
__device__ unsigned short g_x_lo[(size_t)T_TOK * D_DIM];
__device__ unsigned short g_w1t_hi[(size_t)E_NUM * F_DIM * D_DIM];  // [e][f][d]
__device__ unsigned short g_w1t_lo[(size_t)E_NUM * F_DIM * D_DIM];
__device__ unsigned short g_w2t_hi[(size_t)E_NUM * D_DIM * F_DIM];  // [e][d][f]
__device__ unsigned short g_w2t_lo[(size_t)E_NUM * D_DIM * F_DIM];
__device__ unsigned short g_h_hi[(size_t)A_TOT * F_DIM];            // [row][f]
__device__ unsigned short g_h_lo[(size_t)A_TOT * F_DIM];

// ---------------- helpers -----------------------------------------------------
__device__ __forceinline__ uint32_t smem_u32(const void* p) {
    uint32_t a;
    asm("{ .reg .u64 t; cvta.to.shared.u64 t, %1; cvt.u32.u64 %0, t; }"
        : "=r"(a) : "l"(p));
    return a;
}
#define SWZ(o) ((o) ^ (((o) >> 3) & 0x70))

__device__ __forceinline__ void cpa16(uint32_t d, const void* s, uint32_t n) {
    asm volatile("cp.async.cg.shared.global [%0], [%1], 16, %2;"
                 :: "r"(d), "l"(s), "r"(n) : "memory");
}
#define CP_COMMIT() asm volatile("cp.async.commit_group;" ::: "memory")
#define CP_WAIT2()  asm volatile("cp.async.wait_group 2;" ::: "memory")

#define LDSM4(r, a)                                                      \
    asm volatile("ldmatrix.sync.aligned.m8n8.x4.shared.b16 "             \
                 "{%0,%1,%2,%3}, [%4];"                                  \
                 : "=r"((r)[0]), "=r"((r)[1]), "=r"((r)[2]), "=r"((r)[3])\
                 : "r"(a))
#define LDSM2(r, a)                                                      \
    asm volatile("ldmatrix.sync.aligned.m8n8.x2.shared.b16 {%0,%1}, [%2];" \
                 : "=r"((r)[0]), "=r"((r)[1]) : "r"(a))

__device__ __forceinline__ void mma16816(float* c, const uint32_t* a,
                                         const uint32_t* b) {
    asm volatile(
        "mma.sync.aligned.m16n8k16.row.col.f32.bf16.bf16.f32 "
        "{%0,%1,%2,%3}, {%4,%5,%6,%7}, {%8,%9}, {%0,%1,%2,%3};"
        : "+f"(c[0]), "+f"(c[1]), "+f"(c[2]), "+f"(c[3])
        : "r"(a[0]), "r"(a[1]), "r"(a[2]), "r"(a[3]), "r"(b[0]), "r"(b[1]));
}

__device__ __forceinline__ void split_bf(float v, unsigned short& h,
                                         unsigned short& l) {
    __nv_bfloat16 hb = __float2bfloat16(v);
    __nv_bfloat16 lb = __float2bfloat16(v - __bfloat162float(hb));
    h = *reinterpret_cast<unsigned short*>(&hb);
    l = *reinterpret_cast<unsigned short*>(&lb);
}
__device__ __forceinline__ float gelu_tanh(float v) {
    float c = 0.7978845608028654f * (v + 0.044715f * v * v * v);
    return 0.5f * v * (1.0f + tanhf(c));
}

// ---------------- init --------------------------------------------------------
__global__ void zero_kernel(float* __restrict__ out) {
    size_t n = (size_t)T_TOK * D_DIM;
    for (size_t i = (size_t)blockIdx.x * blockDim.x + threadIdx.x; i < n;
         i += (size_t)gridDim.x * blockDim.x)
        out[i] = 0.0f;
    if (blockIdx.x == 0 && threadIdx.x < E_NUM) {
        g_cnt[threadIdx.x] = 0;
        g_cur[threadIdx.x] = 0;
    }
}

// ---------------- router ------------------------------------------------------
__global__ void router_kernel(const float* __restrict__ x,
                              const float* __restrict__ rw) {
    int gwarp = (blockIdx.x * blockDim.x + threadIdx.x) >> 5;
    int lane  = threadIdx.x & 31;
    if (gwarp >= T_TOK) return;
    const float* xr = x + (size_t)gwarp * D_DIM;

    float xv[32];
#pragma unroll
    for (int i = 0; i < 32; i++) xv[i] = xr[lane + 32 * i];

    float logits[E_NUM];
#pragma unroll
    for (int e = 0; e < E_NUM; e++) {
        float s = 0.0f;
#pragma unroll
        for (int i = 0; i < 32; i++)
            s += xv[i] * rw[(lane + 32 * i) * E_NUM + e];
#pragma unroll
        for (int o = 16; o > 0; o >>= 1)
            s += __shfl_xor_sync(0xffffffffu, s, o);
        logits[e] = s;
    }

    if (lane == 0) {
        int i0 = 0;
#pragma unroll
        for (int e = 1; e < E_NUM; e++)
            if (logits[e] > logits[i0]) i0 = e;
        int i1 = (i0 == 0) ? 1 : 0;
#pragma unroll
        for (int e = 0; e < E_NUM; e++) {
            if (e == i0) continue;
            if (logits[e] > logits[i1]) i1 = e;
        }
        float g0 = 1.0f / (1.0f + expf(logits[i1] - logits[i0]));
        float g1 = 1.0f - g0;
        g_top[gwarp][0]  = i0;
        g_top[gwarp][1]  = i1;
        g_gate[gwarp][0] = g0;
        g_gate[gwarp][1] = g1;
        atomicAdd(&g_cnt[i0], 1);
        atomicAdd(&g_cnt[i1], 1);
    }
}

__global__ void offsets_kernel() {
    if (threadIdx.x == 0 && blockIdx.x == 0) {
        int run = 0;
#pragma unroll
        for (int e = 0; e < E_NUM; e++) {
            g_off[e] = run;
            run += g_cnt[e];
            g_cur[e] = 0;
        }
    }
}

__global__ void place_kernel() {
    int t = blockIdx.x * blockDim.x + threadIdx.x;
    if (t >= T_TOK) return;
#pragma unroll
    for (int s = 0; s < 2; s++) {
        int e = g_top[t][s];
        int p = g_off[e] + atomicAdd(&g_cur[e], 1);
        g_rowtok[p]  = t;
        g_rowgate[p] = g_gate[t][s];
    }
}

// ---------------- conversions / transposes ------------------------------------
__global__ void conv_x_kernel(const float* __restrict__ x) {
    size_t v = (size_t)blockIdx.x * blockDim.x + threadIdx.x;
    float4 f = ((const float4*)x)[v];
    ushort4 h, l;
    split_bf(f.x, h.x, l.x);
    split_bf(f.y, h.y, l.y);
    split_bf(f.z, h.z, l.z);
    split_bf(f.w, h.w, l.w);
    ((ushort4*)g_x_hi)[v] = h;
    ((ushort4*)g_x_lo)[v] = l;
}

__global__ void tw1_kernel(const float* __restrict__ w1) {
    __shared__ float t[32][33];
    int e = blockIdx.z, f0 = blockIdx.x * 32, d0 = blockIdx.y * 32;
    int tx = threadIdx.x, ty = threadIdx.y;
#pragma unroll
    for (int r = 0; r < 4; r++)
        t[ty + 8 * r][tx] =
            w1[((size_t)e * D_DIM + d0 + ty + 8 * r) * F_DIM + f0 + tx];
    __syncthreads();
#pragma unroll
    for (int r = 0; r < 4; r++) {
        float v = t[tx][ty + 8 * r];
        unsigned short h, l;
        split_bf(v, h, l);
        size_t idx = ((size_t)e * F_DIM + f0 + ty + 8 * r) * D_DIM + d0 + tx;
        g_w1t_hi[idx] = h;
        g_w1t_lo[idx] = l;
    }
}

__global__ void tw2_kernel(const float* __restrict__ w2) {
    __shared__ float t[32][33];
    int e = blockIdx.z, f0 = blockIdx.x * 32, d0 = blockIdx.y * 32;
    int tx = threadIdx.x, ty = threadIdx.y;
#pragma unroll
    for (int r = 0; r < 4; r++)
        t[ty + 8 * r][tx] =
            w2[((size_t)e * F_DIM + f0 + ty + 8 * r) * D_DIM + d0 + tx];
    __syncthreads();
#pragma unroll
    for (int r = 0; r < 4; r++) {
        float v = t[tx][ty + 8 * r];
        unsigned short h, l;
        split_bf(v, h, l);
        size_t idx = ((size_t)e * D_DIM + d0 + ty + 8 * r) * F_DIM + f0 + tx;
        g_w2t_hi[idx] = h;
        g_w2t_lo[idx] = l;
    }
}

// ---------------- mma.sync GEMM core ------------------------------------------
// CTA tile 128x128, K-chunk 64 (128B rows, SW128), 8 warps (2M x 4N),
// warp tile 64x32, 3-stage cp.async pipeline.
#define STAGE_BYTES 65536
#define SOFF_AH 0
#define SOFF_AL 16384
#define SOFF_BH 32768
#define SOFF_BL 49152
#define NSTAGE  3
#define SMEM_GEMM (NSTAGE * STAGE_BYTES)

#define GEMM_COMPUTE_CHUNK(st)                                              \
    _Pragma("unroll")                                                        \
    for (int ks = 0; ks < 4; ks++) {                                         \
        uint32_t ah[4][4], al[4][4], bh[4][2], bl[4][2];                     \
        uint32_t arow = warpM + (lane & 15);                                 \
        uint32_t acol = ks * 32 + ((lane >> 4) << 4);                        \
        _Pragma("unroll")                                                    \
        for (int mi = 0; mi < 4; mi++) {                                     \
            uint32_t ad = (st) + SOFF_AH + SWZ((arow + 16 * mi) * 128 + acol);\
            LDSM4(ah[mi], ad);                                               \
            LDSM4(al[mi], ad + 16384);                                       \
        }                                                                    \
        uint32_t brow = warpN + (lane & 7);                                  \
        uint32_t bcol = ks * 32 + (((lane >> 3) & 1) << 4);                  \
        _Pragma("unroll")                                                    \
        for (int ni = 0; ni < 4; ni++) {                                     \
            uint32_t bd = (st) + SOFF_BH + SWZ((brow + 8 * ni) * 128 + bcol);\
            LDSM2(bh[ni], bd);                                               \
            LDSM2(bl[ni], bd + 16384);                                       \
        }                                                                    \
        _Pragma("unroll")                                                    \
        for (int ni = 0; ni < 4; ni++)                                       \
            _Pragma("unroll")                                                \
            for (int mi = 0; mi < 4; mi++) {                                 \
                mma16816(acc[mi][ni], ah[mi], bh[ni]);                       \
                mma16816(acc[mi][ni], ah[mi], bl[ni]);                       \
                mma16816(acc[mi][ni], al[mi], bh[ni]);                       \
            }                                                                \
    }

// ---------------- GEMM1: H = gelu(gather(X) @ w1t[e]^T) -----------------------
__global__ __launch_bounds__(256, 1) void gemm1_mma() {
    const int e   = blockIdx.z;
    const int cnt = g_cnt[e];
    const int m0  = blockIdx.x * 128;
    if (m0 >= cnt) return;
    const int base = g_off[e];
    const int n0   = blockIdx.y * 128;

    extern __shared__ char smem[];
    const uint32_t sb = smem_u32(smem);
    const int tid = threadIdx.x, lane = tid & 31, wid = tid >> 5;
    const uint32_t warpM = (wid & 1) * 64, warpN = (wid >> 1) * 32;

    const int colg = tid & 7;
    const int rq   = tid >> 3;
    size_t aoff[4], boff[4];
    uint32_t an[4], dsw[4];
#pragma unroll
    for (int i = 0; i < 4; i++) {
        int r = rq + 32 * i;
        dsw[i] = SWZ((uint32_t)(r * 128 + colg * 16));
        bool v = (m0 + r) < cnt;
        aoff[i] = v ? (size_t)g_rowtok[base + m0 + r] * D_DIM : 0;
        an[i]   = v ? 16u : 0u;
        boff[i] = ((size_t)e * F_DIM + n0 + r) * D_DIM;
    }

    float acc[4][4][4];
#pragma unroll
    for (int a = 0; a < 4; a++)
#pragma unroll
        for (int b = 0; b < 4; b++)
#pragma unroll
            for (int c = 0; c < 4; c++) acc[a][b][c] = 0.0f;

    const int NC = D_DIM / 64;  // 16
#pragma unroll
    for (int c = 0; c < NSTAGE; c++) {
        uint32_t st = sb + c * STAGE_BYTES;
        int k0 = c * 64 + colg * 8;
#pragma unroll
        for (int i = 0; i < 4; i++) {
            cpa16(st + SOFF_AH + dsw[i], g_x_hi + aoff[i] + k0, an[i]);
            cpa16(st + SOFF_AL + dsw[i], g_x_lo + aoff[i] + k0, an[i]);
            cpa16(st + SOFF_BH + dsw[i], g_w1t_hi + boff[i] + k0, 16u);
            cpa16(st + SOFF_BL + dsw[i], g_w1t_lo + boff[i] + k0, 16u);
        }
        CP_COMMIT();
    }

    for (int c = 0; c < NC; c++) {
        CP_WAIT2();
        __syncthreads();
        uint32_t st = sb + (c % 3) * STAGE_BYTES;
        GEMM_COMPUTE_CHUNK(st)
        __syncthreads();
        int cn = c + NSTAGE;
        if (cn < NC) {
            uint32_t st2 = sb + (cn % 3) * STAGE_BYTES;
            int k0 = cn * 64 + colg * 8;
#pragma unroll
            for (int i = 0; i < 4; i++) {
                cpa16(st2 + SOFF_AH + dsw[i], g_x_hi + aoff[i] + k0, an[i]);
                cpa16(st2 + SOFF_AL + dsw[i], g_x_lo + aoff[i] + k0, an[i]);
                cpa16(st2 + SOFF_BH + dsw[i], g_w1t_hi + boff[i] + k0, 16u);
                cpa16(st2 + SOFF_BL + dsw[i], g_w1t_lo + boff[i] + k0, 16u);
            }
        }
        CP_COMMIT();
    }

    // epilogue: gelu -> hi/lo split -> store to g_h planes
#pragma unroll
    for (int mi = 0; mi < 4; mi++)
#pragma unroll
        for (int p = 0; p < 2; p++) {
            int gm = m0 + (int)warpM + mi * 16 + (lane >> 2) + 8 * p;
            if (gm < cnt) {
                size_t rb = (size_t)(base + gm) * F_DIM;
#pragma unroll
                for (int ni = 0; ni < 4; ni++) {
                    int n = n0 + (int)warpN + ni * 8 + 2 * (lane & 3);
                    float v0 = gelu_tanh(acc[mi][ni][2 * p]);
                    float v1 = gelu_tanh(acc[mi][ni][2 * p + 1]);
                    unsigned short h0, l0, h1, l1;
                    split_bf(v0, h0, l0);
                    split_bf(v1, h1, l1);
                    *(ushort2*)(g_h_hi + rb + n) = make_ushort2(h0, h1);
                    *(ushort2*)(g_h_lo + rb + n) = make_ushort2(l0, l1);
                }
            }
        }
}

// ---------------- GEMM2: out[tok] += gate * (H @ w2t[e]^T) --------------------
__global__ __launch_bounds__(256, 1) void gemm2_mma(float* __restrict__ out) {
    const int e   = blockIdx.z;
    const int cnt = g_cnt[e];
    const int m0  = blockIdx.x * 128;
    if (m0 >= cnt) return;
    const int base = g_off[e];
    const int d0   = blockIdx.y * 128;

    extern __shared__ char smem[];
    const uint32_t sb = smem_u32(smem);
    const int tid = threadIdx.x, lane = tid & 31, wid = tid >> 5;
    const uint32_t warpM = (wid & 1) * 64, warpN = (wid >> 1) * 32;

    const int colg = tid & 7;
    const int rq   = tid >> 3;
    size_t aoff[4], boff[4];
    uint32_t an[4], dsw[4];
#pragma unroll
    for (int i = 0; i < 4; i++) {
        int r = rq + 32 * i;
        dsw[i] = SWZ((uint32_t)(r * 128 + colg * 16));
        bool v = (m0 + r) < cnt;
        aoff[i] = v ? (size_t)(base + m0 + r) * F_DIM : 0;
        an[i]   = v ? 16u : 0u;
        boff[i] = ((size_t)e * D_DIM + d0 + r) * F_DIM;
    }

    float acc[4][4][4];
#pragma unroll
    for (int a = 0; a < 4; a++)
#pragma unroll
        for (int b = 0; b < 4; b++)
#pragma unroll
            for (int c = 0; c < 4; c++) acc[a][b][c] = 0.0f;

    const int NC = F_DIM / 64;  // 64
#pragma unroll
    for (int c = 0; c < NSTAGE; c++) {
        uint32_t st = sb + c * STAGE_BYTES;
        int k0 = c * 64 + colg * 8;
#pragma unroll
        for (int i = 0; i < 4; i++) {
            cpa16(st + SOFF_AH + dsw[i], g_h_hi + aoff[i] + k0, an[i]);
            cpa16(st + SOFF_AL + dsw[i], g_h_lo + aoff[i] + k0, an[i]);
            cpa16(st + SOFF_BH + dsw[i], g_w2t_hi + boff[i] + k0, 16u);
            cpa16(st + SOFF_BL + dsw[i], g_w2t_lo + boff[i] + k0, 16u);
        }
        CP_COMMIT();
    }

    for (int c = 0; c < NC; c++) {
        CP_WAIT2();
        __syncthreads();
        uint32_t st = sb + (c % 3) * STAGE_BYTES;
        GEMM_COMPUTE_CHUNK(st)
        __syncthreads();
        int cn = c + NSTAGE;
        if (cn < NC) {
            uint32_t st2 = sb + (cn % 3) * STAGE_BYTES;
            int k0 = cn * 64 + colg * 8;
#pragma unroll
            for (int i = 0; i < 4; i++) {
                cpa16(st2 + SOFF_AH + dsw[i], g_h_hi + aoff[i] + k0, an[i]);
                cpa16(st2 + SOFF_AL + dsw[i], g_h_lo + aoff[i] + k0, an[i]);
                cpa16(st2 + SOFF_BH + dsw[i], g_w2t_hi + boff[i] + k0, 16u);
                cpa16(st2 + SOFF_BL + dsw[i], g_w2t_lo + boff[i] + k0, 16u);
            }
        }
        CP_COMMIT();
    }

    // epilogue: gate-scaled atomic scatter to out[tok][d]
#pragma unroll
    for (int mi = 0; mi < 4; mi++)
#pragma unroll
        for (int p = 0; p < 2; p++) {
            int gm = m0 + (int)warpM + mi * 16 + (lane >> 2) + 8 * p;
            if (gm < cnt) {
                int   tok = g_rowtok[base + gm];
                float g   = g_rowgate[base + gm];
                float* orow = out + (size_t)tok * D_DIM;
#pragma unroll
                for (int ni = 0; ni < 4; ni++) {
                    int d = d0 + (int)warpN + ni * 8 + 2 * (lane & 3);
                    atomicAdd(orow + d,     g * acc[mi][ni][2 * p]);
                    atomicAdd(orow + d + 1, g * acc[mi][ni][2 * p + 1]);
                }
            }
        }
}

// ---------------- launch ------------------------------------------------------
extern "C" void kernel_launch(void* const* d_in, const int* in_sizes, int n_in,
                              void* d_out, int out_size) {
    const float* x  = (const float*)d_in[0];
    const float* rw = (const float*)d_in[1];
    const float* w1 = (const float*)d_in[2];
    const float* w2 = (const float*)d_in[3];
    float*       out = (float*)d_out;

    static bool attr_set = false;
    if (!attr_set) {
        cudaFuncSetAttribute(gemm1_mma, cudaFuncAttributeMaxDynamicSharedMemorySize,
                             SMEM_GEMM);
        cudaFuncSetAttribute(gemm2_mma, cudaFuncAttributeMaxDynamicSharedMemorySize,
                             SMEM_GEMM);
        attr_set = true;
    }

    zero_kernel<<<1024, 256>>>(out);
    conv_x_kernel<<<(T_TOK * D_DIM / 4) / 256, 256>>>(x);
    tw1_kernel<<<dim3(F_DIM / 32, D_DIM / 32, E_NUM), dim3(32, 8)>>>(w1);
    tw2_kernel<<<dim3(F_DIM / 32, D_DIM / 32, E_NUM), dim3(32, 8)>>>(w2);
    router_kernel<<<(T_TOK * 32) / 256, 256>>>(x, rw);
    offsets_kernel<<<1, 32>>>();
    place_kernel<<<T_TOK / 256, 256>>>();

    gemm1_mma<<<dim3(64, F_DIM / 128, E_NUM), 256, SMEM_GEMM>>>();
    gemm2_mma<<<dim3(64, D_DIM / 128, E_NUM), 256, SMEM_GEMM>>>(out);
}